// round 6
// baseline (speedup 1.0000x reference)
#include <cuda_runtime.h>

// ChamferLoss fused single-pass, B=4, N=M=8192, 3D.
// t-space: t = n2_j - 2 p_i.q_j (3 wide FMA2 per 2 pairs, NO per-pair seed add).
// Row-min over t (n1 added once per i at flush). Col-min: d = n1 + t via scalar
// FFMA-imm (rt=1) then FMNMX. Col warp-reduce via REDUX.MIN.s32.

#define BB 4
#define NPTS 8192
#define MPTS 8192
#define THREADS 128
#define IPT 16
#define KKN (IPT / 2)
#define ITILES (NPTS / (THREADS * IPT))   // 4
#define JT 32
#define JCH (MPTS / JT)                   // 256
#define G 8

typedef unsigned long long u64;

__device__ float g_d1[BB * NPTS];
__device__ float g_d2[BB * MPTS];

#define PACK2(o, lo, hi)   asm("mov.b64 %0,{%1,%2};" : "=l"(o) : "f"(lo), "f"(hi))
#define UNPACK2(lo, hi, i) asm("mov.b64 {%0,%1},%2;" : "=f"(lo), "=f"(hi) : "l"(i))
#define FMA2(d, a, b, c)   asm("fma.rn.f32x2 %0,%1,%2,%3;" : "=l"(d) : "l"(a), "l"(b), "l"(c))
// d = a * 1.0 + b ; immediate multiplier -> FFMA-imm form (rt 1)
#define FFMAIMM(d, a, b)   asm("fma.rn.f32 %0,%1,0f3F800000,%2;" : "=f"(d) : "f"(a), "f"(b))

__global__ void chamfer_init_kernel(float* out) {
    int idx = blockIdx.x * blockDim.x + threadIdx.x;   // 16384 threads
    int4 inf4 = make_int4(0x7f800000, 0x7f800000, 0x7f800000, 0x7f800000);
    if (idx < (BB * NPTS) / 4) ((int4*)g_d1)[idx] = inf4;
    else ((int4*)g_d2)[idx - (BB * NPTS) / 4] = inf4;
    if (idx == 0) out[0] = 0.f;
}

__global__ void __launch_bounds__(THREADS) chamfer_fused_kernel(
    const float* __restrict__ xyz1, const float* __restrict__ xyz2)
{
    __shared__ ulonglong2 tA[JCH];   // (-2x,-2x | -2y,-2y)
    __shared__ ulonglong2 tB[JCH];   // (-2z,-2z |  n2, n2)
    __shared__ int colmn[JCH];

    const int tid = threadIdx.x;
    const int lane = tid & 31;
    const int b = blockIdx.z;
    const int iBase = blockIdx.x * (THREADS * IPT);
    const int jBase = blockIdx.y * JCH;
    const float* __restrict__ P = xyz1 + (size_t)b * NPTS * 3;
    const float* __restrict__ Q = xyz2 + (size_t)b * MPTS * 3;

    u64 ax2[KKN], ay2[KKN], az2[KKN];
    float n1s[IPT], mn[IPT];
#pragma unroll
    for (int kk = 0; kk < KKN; kk++) {
        int i0 = iBase + tid + (2 * kk) * THREADS;
        int i1 = iBase + tid + (2 * kk + 1) * THREADS;
        float x0 = P[i0 * 3], y0 = P[i0 * 3 + 1], z0 = P[i0 * 3 + 2];
        float x1 = P[i1 * 3], y1 = P[i1 * 3 + 1], z1 = P[i1 * 3 + 2];
        PACK2(ax2[kk], x0, x1);
        PACK2(ay2[kk], y0, y1);
        PACK2(az2[kk], z0, z1);
        n1s[2 * kk]     = fmaf(x0, x0, fmaf(y0, y0, z0 * z0));
        n1s[2 * kk + 1] = fmaf(x1, x1, fmaf(y1, y1, z1 * z1));
        mn[2 * kk] = 3.4e38f;
        mn[2 * kk + 1] = 3.4e38f;
    }

    for (int jj = tid; jj < JCH; jj += THREADS) {
        int j = jBase + jj;
        float x = Q[j * 3], y = Q[j * 3 + 1], z = Q[j * 3 + 2];
        float n2 = fmaf(x, x, fmaf(y, y, z * z));
        float nx = -2.f * x, ny = -2.f * y, nz = -2.f * z;
        u64 X2, Y2, Z2, W2;
        PACK2(X2, nx, nx);
        PACK2(Y2, ny, ny);
        PACK2(Z2, nz, nz);
        PACK2(W2, n2, n2);
        tA[jj] = make_ulonglong2(X2, Y2);
        tB[jj] = make_ulonglong2(Z2, W2);
        colmn[jj] = 0x7f800000;
    }
    __syncthreads();

    for (int jj0 = 0; jj0 < JCH; jj0 += G) {
        int cvi[G];
#pragma unroll
        for (int g = 0; g < G; g++) {
            ulonglong2 ba = tA[jj0 + g];   // X2, Y2
            ulonglong2 bb = tB[jj0 + g];   // Z2, W2 (= n2 dup)
            float c0 = 3.4e38f, c1 = 3.4e38f;
#pragma unroll
            for (int kk = 0; kk < KKN; kk++) {
                u64 t;
                FMA2(t, bb.x, az2[kk], bb.y);   // t = n2 - 2z*az
                FMA2(t, ba.y, ay2[kk], t);      //   -= 2y*ay
                FMA2(t, ba.x, ax2[kk], t);      //   -= 2x*ax
                float t0, t1;
                UNPACK2(t0, t1, t);
                mn[2 * kk]     = fminf(mn[2 * kk], t0);      // row-min, t-space
                mn[2 * kk + 1] = fminf(mn[2 * kk + 1], t1);
                float u0, u1;
                FFMAIMM(u0, n1s[2 * kk], t0);   // d^2 = n1 + t (FFMA-imm)
                FFMAIMM(u1, n1s[2 * kk + 1], t1);
                c0 = fminf(c0, u0);
                c1 = fminf(c1, u1);
            }
            cvi[g] = __float_as_int(fmaxf(fminf(c0, c1), 0.f));
        }
#pragma unroll
        for (int g = 0; g < G; g++)
            cvi[g] = __reduce_min_sync(0xffffffffu, cvi[g]);   // REDUX.MIN.s32
        if (lane < G) {
            int myv = cvi[0];
#pragma unroll
            for (int g = 1; g < G; g++)
                if (lane == g) myv = cvi[g];
            atomicMin(&colmn[jj0 + lane], myv);
        }
    }
    __syncthreads();

    for (int jj = tid; jj < JCH; jj += THREADS)
        atomicMin((int*)&g_d2[b * MPTS + jBase + jj], colmn[jj]);

#pragma unroll
    for (int kk = 0; kk < KKN; kk++) {
        int i0 = iBase + tid + (2 * kk) * THREADS;
        int i1 = iBase + tid + (2 * kk + 1) * THREADS;
        float d0 = fmaxf(mn[2 * kk] + n1s[2 * kk], 0.f);
        float d1 = fmaxf(mn[2 * kk + 1] + n1s[2 * kk + 1], 0.f);
        atomicMin((int*)&g_d1[b * NPTS + i0], __float_as_int(d0));
        atomicMin((int*)&g_d1[b * NPTS + i1], __float_as_int(d1));
    }
}

__global__ void chamfer_reduce_kernel(float* __restrict__ out) {
    const float4* src = (const float4*)((blockIdx.x < 32) ? g_d1 : g_d2);
    int base = (blockIdx.x & 31) * 256;   // 256 float4 = 1024 floats per block
    float s = 0.f;
    for (int k = threadIdx.x; k < 256; k += 256) {
        float4 v = src[base + k];
        s += (v.x + v.y) + (v.z + v.w);
    }
    s *= (1.f / (BB * NPTS));
#pragma unroll
    for (int o = 16; o > 0; o >>= 1) s += __shfl_down_sync(0xffffffffu, s, o);
    __shared__ float sh[8];
    if ((threadIdx.x & 31) == 0) sh[threadIdx.x >> 5] = s;
    __syncthreads();
    if (threadIdx.x < 8) {
        float v = sh[threadIdx.x];
#pragma unroll
        for (int o = 4; o > 0; o >>= 1) v += __shfl_down_sync(0xffu, v, o);
        if (threadIdx.x == 0) atomicAdd(out, v);
    }
}

extern "C" void kernel_launch(void* const* d_in, const int* in_sizes, int n_in,
                              void* d_out, int out_size) {
    const float* xyz1 = (const float*)d_in[0];
    const float* xyz2 = (const float*)d_in[1];
    float* out = (float*)d_out;

    chamfer_init_kernel<<<64, 256>>>(out);

    dim3 grid(ITILES, JT, BB);  // (4, 32, 4) = 512 blocks
    chamfer_fused_kernel<<<grid, THREADS>>>(xyz1, xyz2);

    chamfer_reduce_kernel<<<64, 256>>>(out);
}

// round 7
// speedup vs baseline: 1.0099x; 1.0099x over previous
#include <cuda_runtime.h>

// ChamferLoss fused single-pass, B=4, N=M=8192, 3D.
// dist^2 = (n1_i + n2_j) - 2 p_i.q_j, packed f32x2 (2 i-points per op) -> at the
// fp32 wide-fma roofline (~0.25 cyc/pair). Overhead removed via deterministic
// partial buffers (plain STG, no init kernel, no global atomics in hot path).

#define BB 4
#define NPTS 8192
#define MPTS 8192
#define THREADS 128
#define IPT 16
#define KKN (IPT / 2)
#define ITILES (NPTS / (THREADS * IPT))   // 4
#define JT 64
#define JCH (MPTS / JT)                   // 128
#define G 8
#define CSLABS (ITILES * 4)               // 16 col slabs (per i-tile x warp)

typedef unsigned long long u64;

__device__ float g_p1[JT][BB * NPTS];      // row-min partials per j-slab (8 MB)
__device__ float g_p2[CSLABS][BB * MPTS];  // col-min partials per (itile,warp) (2 MB)

#define PACK2(o, lo, hi)   asm("mov.b64 %0,{%1,%2};" : "=l"(o) : "f"(lo), "f"(hi))
#define UNPACK2(lo, hi, i) asm("mov.b64 {%0,%1},%2;" : "=f"(lo), "=f"(hi) : "l"(i))
#define FMA2(d, a, b, c)   asm("fma.rn.f32x2 %0,%1,%2,%3;" : "=l"(d) : "l"(a), "l"(b), "l"(c))
#define ADD2(d, a, b)      asm("add.rn.f32x2 %0,%1,%2;" : "=l"(d) : "l"(a), "l"(b))

__global__ void __launch_bounds__(THREADS) chamfer_fused_kernel(
    const float* __restrict__ xyz1, const float* __restrict__ xyz2, float* __restrict__ out)
{
    __shared__ ulonglong2 tA[JCH];   // (-2x,-2x | -2y,-2y)
    __shared__ ulonglong2 tB[JCH];   // (-2z,-2z |  n2, n2)

    const int tid = threadIdx.x;
    const int lane = tid & 31;
    const int warp = tid >> 5;
    const int b = blockIdx.z;
    const int iBase = blockIdx.x * (THREADS * IPT);
    const int jBase = blockIdx.y * JCH;
    const float* __restrict__ P = xyz1 + (size_t)b * NPTS * 3;
    const float* __restrict__ Q = xyz2 + (size_t)b * MPTS * 3;

    // Zero the output once per launch; stream order puts this before reduce.
    if (blockIdx.x == 0 && blockIdx.y == 0 && blockIdx.z == 0 && tid == 0)
        out[0] = 0.f;

    u64 ax2[KKN], ay2[KKN], az2[KKN], n12[KKN];
    float mn[IPT];
#pragma unroll
    for (int kk = 0; kk < KKN; kk++) {
        int i0 = iBase + tid + (2 * kk) * THREADS;
        int i1 = iBase + tid + (2 * kk + 1) * THREADS;
        float x0 = P[i0 * 3], y0 = P[i0 * 3 + 1], z0 = P[i0 * 3 + 2];
        float x1 = P[i1 * 3], y1 = P[i1 * 3 + 1], z1 = P[i1 * 3 + 2];
        PACK2(ax2[kk], x0, x1);
        PACK2(ay2[kk], y0, y1);
        PACK2(az2[kk], z0, z1);
        float n0 = fmaf(x0, x0, fmaf(y0, y0, z0 * z0));
        float n1 = fmaf(x1, x1, fmaf(y1, y1, z1 * z1));
        PACK2(n12[kk], n0, n1);
        mn[2 * kk] = 3.4e38f;
        mn[2 * kk + 1] = 3.4e38f;
    }

    for (int jj = tid; jj < JCH; jj += THREADS) {
        int j = jBase + jj;
        float x = Q[j * 3], y = Q[j * 3 + 1], z = Q[j * 3 + 2];
        float n2 = fmaf(x, x, fmaf(y, y, z * z));
        float nx = -2.f * x, ny = -2.f * y, nz = -2.f * z;
        u64 X2, Y2, Z2, W2;
        PACK2(X2, nx, nx);
        PACK2(Y2, ny, ny);
        PACK2(Z2, nz, nz);
        PACK2(W2, n2, n2);
        tA[jj] = make_ulonglong2(X2, Y2);
        tB[jj] = make_ulonglong2(Z2, W2);
    }
    __syncthreads();

    float* __restrict__ colOut = g_p2[blockIdx.x * 4 + warp] + b * MPTS + jBase;

    for (int jj0 = 0; jj0 < JCH; jj0 += G) {
        float cv[G];
#pragma unroll
        for (int g = 0; g < G; g++) {
            ulonglong2 ba = tA[jj0 + g];   // X2, Y2
            ulonglong2 bb = tB[jj0 + g];   // Z2, W2
            float c0 = 3.4e38f, c1 = 3.4e38f;
#pragma unroll
            for (int kk = 0; kk < KKN; kk++) {
                u64 w, t;
                ADD2(w, n12[kk], bb.y);        // n1 + n2
                FMA2(t, bb.x, az2[kk], w);     // += -2z*az
                FMA2(t, ba.y, ay2[kk], t);     // += -2y*ay
                FMA2(t, ba.x, ax2[kk], t);     // += -2x*ax -> dist^2 x2
                float t0, t1;
                UNPACK2(t0, t1, t);
                mn[2 * kk]     = fminf(mn[2 * kk], t0);
                mn[2 * kk + 1] = fminf(mn[2 * kk + 1], t1);
                c0 = fminf(c0, t0);
                c1 = fminf(c1, t1);
            }
            cv[g] = fminf(c0, c1);
        }
        // 8 pipelined butterfly chains
#pragma unroll
        for (int o = 16; o > 0; o >>= 1)
#pragma unroll
            for (int g = 0; g < G; g++)
                cv[g] = fminf(cv[g], __shfl_xor_sync(0xffffffffu, cv[g], o));
        // lane g holds result g -> plain store into this warp's own slab
        float myv = cv[0];
#pragma unroll
        for (int g = 1; g < G; g++)
            if (lane == g) myv = cv[g];
        if (lane < G)
            colOut[jj0 + lane] = myv;
    }

    // Row-min partials: plain store into this block's j-slab.
    float* __restrict__ rowOut = g_p1[blockIdx.y] + b * NPTS;
#pragma unroll
    for (int kk = 0; kk < KKN; kk++) {
        int i0 = iBase + tid + (2 * kk) * THREADS;
        int i1 = iBase + tid + (2 * kk + 1) * THREADS;
        rowOut[i0] = mn[2 * kk];
        rowOut[i1] = mn[2 * kk + 1];
    }
}

// 64 blocks x 256 threads; gid < 8192: row float4 (min over JT slabs),
// else col float4 (min over CSLABS slabs). Then scaled sum -> atomicAdd.
__global__ void chamfer_reduce_kernel(float* __restrict__ out) {
    int gid = blockIdx.x * blockDim.x + threadIdx.x;   // 0..16383
    float4 m = make_float4(3.4e38f, 3.4e38f, 3.4e38f, 3.4e38f);
    if (gid < (BB * NPTS) / 4) {
        const float4* base = (const float4*)g_p1[0] + gid;
#pragma unroll 4
        for (int s = 0; s < JT; s++) {
            float4 v = base[(size_t)s * (BB * NPTS / 4)];
            m.x = fminf(m.x, v.x); m.y = fminf(m.y, v.y);
            m.z = fminf(m.z, v.z); m.w = fminf(m.w, v.w);
        }
    } else {
        const float4* base = (const float4*)g_p2[0] + (gid - (BB * NPTS) / 4);
#pragma unroll
        for (int s = 0; s < CSLABS; s++) {
            float4 v = base[(size_t)s * (BB * MPTS / 4)];
            m.x = fminf(m.x, v.x); m.y = fminf(m.y, v.y);
            m.z = fminf(m.z, v.z); m.w = fminf(m.w, v.w);
        }
    }
    float s = ((m.x + m.y) + (m.z + m.w)) * (1.f / (BB * NPTS));
#pragma unroll
    for (int o = 16; o > 0; o >>= 1) s += __shfl_down_sync(0xffffffffu, s, o);
    __shared__ float sh[8];
    if ((threadIdx.x & 31) == 0) sh[threadIdx.x >> 5] = s;
    __syncthreads();
    if (threadIdx.x < 8) {
        float v = sh[threadIdx.x];
#pragma unroll
        for (int o = 4; o > 0; o >>= 1) v += __shfl_down_sync(0xffu, v, o);
        if (threadIdx.x == 0) atomicAdd(out, v);
    }
}

extern "C" void kernel_launch(void* const* d_in, const int* in_sizes, int n_in,
                              void* d_out, int out_size) {
    const float* xyz1 = (const float*)d_in[0];
    const float* xyz2 = (const float*)d_in[1];
    float* out = (float*)d_out;

    dim3 grid(ITILES, JT, BB);  // (4, 64, 4) = 1024 blocks
    chamfer_fused_kernel<<<grid, THREADS>>>(xyz1, xyz2, out);

    chamfer_reduce_kernel<<<64, 256>>>(out);
}

// round 8
// speedup vs baseline: 1.0597x; 1.0494x over previous
#include <cuda_runtime.h>

// ChamferLoss fused single-pass, B=4, N=M=8192, 3D.
// Pair kernel: packed f32x2 (2 i-points/op), deterministic partial buffers
// (plain STG, no init kernel, no atomics in hot path). Reduce: 256-block
// slab-split min + shfl combine (fixes R7's 64-block latency-starved reduce).

#define BB 4
#define NPTS 8192
#define MPTS 8192
#define THREADS 128
#define IPT 16
#define KKN (IPT / 2)
#define ITILES (NPTS / (THREADS * IPT))   // 4
#define JT 64
#define JCH (MPTS / JT)                   // 128
#define G 8
#define CSLABS (ITILES * 4)               // 16 col slabs
#define SLAB4 (BB * NPTS / 4)             // 8192 float4 per slab

typedef unsigned long long u64;

__device__ float g_p1[JT][BB * NPTS];      // row-min partials per j-slab (8 MB)
__device__ float g_p2[CSLABS][BB * MPTS];  // col-min partials (2 MB)

#define PACK2(o, lo, hi)   asm("mov.b64 %0,{%1,%2};" : "=l"(o) : "f"(lo), "f"(hi))
#define UNPACK2(lo, hi, i) asm("mov.b64 {%0,%1},%2;" : "=f"(lo), "=f"(hi) : "l"(i))
#define FMA2(d, a, b, c)   asm("fma.rn.f32x2 %0,%1,%2,%3;" : "=l"(d) : "l"(a), "l"(b), "l"(c))
#define ADD2(d, a, b)      asm("add.rn.f32x2 %0,%1,%2;" : "=l"(d) : "l"(a), "l"(b))

__global__ void __launch_bounds__(THREADS) chamfer_fused_kernel(
    const float* __restrict__ xyz1, const float* __restrict__ xyz2, float* __restrict__ out)
{
    __shared__ ulonglong2 tA[JCH];   // (-2x,-2x | -2y,-2y)
    __shared__ ulonglong2 tB[JCH];   // (-2z,-2z |  n2, n2)

    const int tid = threadIdx.x;
    const int lane = tid & 31;
    const int warp = tid >> 5;
    const int b = blockIdx.z;
    const int iBase = blockIdx.x * (THREADS * IPT);
    const int jBase = blockIdx.y * JCH;
    const float* __restrict__ P = xyz1 + (size_t)b * NPTS * 3;
    const float* __restrict__ Q = xyz2 + (size_t)b * MPTS * 3;

    if (blockIdx.x == 0 && blockIdx.y == 0 && blockIdx.z == 0 && tid == 0)
        out[0] = 0.f;

    u64 ax2[KKN], ay2[KKN], az2[KKN], n12[KKN];
    float mn[IPT];
#pragma unroll
    for (int kk = 0; kk < KKN; kk++) {
        int i0 = iBase + tid + (2 * kk) * THREADS;
        int i1 = iBase + tid + (2 * kk + 1) * THREADS;
        float x0 = P[i0 * 3], y0 = P[i0 * 3 + 1], z0 = P[i0 * 3 + 2];
        float x1 = P[i1 * 3], y1 = P[i1 * 3 + 1], z1 = P[i1 * 3 + 2];
        PACK2(ax2[kk], x0, x1);
        PACK2(ay2[kk], y0, y1);
        PACK2(az2[kk], z0, z1);
        float n0 = fmaf(x0, x0, fmaf(y0, y0, z0 * z0));
        float n1 = fmaf(x1, x1, fmaf(y1, y1, z1 * z1));
        PACK2(n12[kk], n0, n1);
        mn[2 * kk] = 3.4e38f;
        mn[2 * kk + 1] = 3.4e38f;
    }

    for (int jj = tid; jj < JCH; jj += THREADS) {
        int j = jBase + jj;
        float x = Q[j * 3], y = Q[j * 3 + 1], z = Q[j * 3 + 2];
        float n2 = fmaf(x, x, fmaf(y, y, z * z));
        float nx = -2.f * x, ny = -2.f * y, nz = -2.f * z;
        u64 X2, Y2, Z2, W2;
        PACK2(X2, nx, nx);
        PACK2(Y2, ny, ny);
        PACK2(Z2, nz, nz);
        PACK2(W2, n2, n2);
        tA[jj] = make_ulonglong2(X2, Y2);
        tB[jj] = make_ulonglong2(Z2, W2);
    }
    __syncthreads();

    float* __restrict__ colOut = g_p2[blockIdx.x * 4 + warp] + b * MPTS + jBase;

    for (int jj0 = 0; jj0 < JCH; jj0 += G) {
        float cv[G];
#pragma unroll
        for (int g = 0; g < G; g++) {
            ulonglong2 ba = tA[jj0 + g];
            ulonglong2 bb = tB[jj0 + g];
            float c0 = 3.4e38f, c1 = 3.4e38f;
#pragma unroll
            for (int kk = 0; kk < KKN; kk++) {
                u64 w, t;
                ADD2(w, n12[kk], bb.y);        // n1 + n2
                FMA2(t, bb.x, az2[kk], w);     // += -2z*az
                FMA2(t, ba.y, ay2[kk], t);     // += -2y*ay
                FMA2(t, ba.x, ax2[kk], t);     // += -2x*ax -> dist^2 x2
                float t0, t1;
                UNPACK2(t0, t1, t);
                mn[2 * kk]     = fminf(mn[2 * kk], t0);
                mn[2 * kk + 1] = fminf(mn[2 * kk + 1], t1);
                c0 = fminf(c0, t0);
                c1 = fminf(c1, t1);
            }
            cv[g] = fminf(c0, c1);
        }
#pragma unroll
        for (int o = 16; o > 0; o >>= 1)
#pragma unroll
            for (int g = 0; g < G; g++)
                cv[g] = fminf(cv[g], __shfl_xor_sync(0xffffffffu, cv[g], o));
        float myv = cv[0];
#pragma unroll
        for (int g = 1; g < G; g++)
            if (lane == g) myv = cv[g];
        if (lane < G)
            colOut[jj0 + lane] = myv;
    }

    float* __restrict__ rowOut = g_p1[blockIdx.y] + b * NPTS;
#pragma unroll
    for (int kk = 0; kk < KKN; kk++) {
        int i0 = iBase + tid + (2 * kk) * THREADS;
        int i1 = iBase + tid + (2 * kk + 1) * THREADS;
        rowOut[i0] = mn[2 * kk];
        rowOut[i1] = mn[2 * kk + 1];
    }
}

// 256 blocks x 256 threads. 4 threads per float4 column (q = gid&3), each
// scans a quarter of the slabs; combine via in-warp shfl butterfly.
__global__ void chamfer_reduce_kernel(float* __restrict__ out) {
    int gid = blockIdx.x * blockDim.x + threadIdx.x;   // 0..65535
    int col = gid >> 2;                                // float4 column 0..16383
    int q = gid & 3;
    float4 m = make_float4(3.4e38f, 3.4e38f, 3.4e38f, 3.4e38f);
    if (col < SLAB4) {
        const float4* base = (const float4*)g_p1[0] + col;
#pragma unroll
        for (int s = 0; s < JT / 4; s++) {
            float4 v = base[(size_t)(q * (JT / 4) + s) * SLAB4];
            m.x = fminf(m.x, v.x); m.y = fminf(m.y, v.y);
            m.z = fminf(m.z, v.z); m.w = fminf(m.w, v.w);
        }
    } else {
        const float4* base = (const float4*)g_p2[0] + (col - SLAB4);
#pragma unroll
        for (int s = 0; s < CSLABS / 4; s++) {
            float4 v = base[(size_t)(q * (CSLABS / 4) + s) * SLAB4];
            m.x = fminf(m.x, v.x); m.y = fminf(m.y, v.y);
            m.z = fminf(m.z, v.z); m.w = fminf(m.w, v.w);
        }
    }
    // combine the 4 slab-quarters (lanes differing in low 2 bits)
#pragma unroll
    for (int o = 1; o <= 2; o <<= 1) {
        m.x = fminf(m.x, __shfl_xor_sync(0xffffffffu, m.x, o));
        m.y = fminf(m.y, __shfl_xor_sync(0xffffffffu, m.y, o));
        m.z = fminf(m.z, __shfl_xor_sync(0xffffffffu, m.z, o));
        m.w = fminf(m.w, __shfl_xor_sync(0xffffffffu, m.w, o));
    }
    float s = (q == 0) ? ((m.x + m.y) + (m.z + m.w)) * (1.f / (BB * NPTS)) : 0.f;
#pragma unroll
    for (int o = 16; o > 0; o >>= 1) s += __shfl_down_sync(0xffffffffu, s, o);
    __shared__ float sh[8];
    if ((threadIdx.x & 31) == 0) sh[threadIdx.x >> 5] = s;
    __syncthreads();
    if (threadIdx.x < 8) {
        float v = sh[threadIdx.x];
#pragma unroll
        for (int o = 4; o > 0; o >>= 1) v += __shfl_down_sync(0xffu, v, o);
        if (threadIdx.x == 0) atomicAdd(out, v);
    }
}

extern "C" void kernel_launch(void* const* d_in, const int* in_sizes, int n_in,
                              void* d_out, int out_size) {
    const float* xyz1 = (const float*)d_in[0];
    const float* xyz2 = (const float*)d_in[1];
    float* out = (float*)d_out;

    dim3 grid(ITILES, JT, BB);  // (4, 64, 4) = 1024 blocks
    chamfer_fused_kernel<<<grid, THREADS>>>(xyz1, xyz2, out);

    chamfer_reduce_kernel<<<256, 256>>>(out);
}

// round 9
// speedup vs baseline: 1.1231x; 1.0598x over previous
#include <cuda_runtime.h>

// ChamferLoss fused single-pass, B=4, N=M=8192, 3D.
// Pair kernel: packed f32x2 (2 i-points/op) at the fp32 wide-fma roofline;
// deterministic partial buffers (plain STG, no init kernel, no atomics in hot
// path); col-min warp reduction via REDUX.MIN.s32 (clamped >=0 keeps s32 order).
// Reduce: 512-block slab-split min + 3-level shfl combine.

#define BB 4
#define NPTS 8192
#define MPTS 8192
#define THREADS 128
#define IPT 16
#define KKN (IPT / 2)
#define ITILES (NPTS / (THREADS * IPT))   // 4
#define JT 64
#define JCH (MPTS / JT)                   // 128
#define G 8
#define CSLABS (ITILES * 4)               // 16 col slabs
#define SLAB4 (BB * NPTS / 4)             // 8192 float4 per slab

typedef unsigned long long u64;

__device__ float g_p1[JT][BB * NPTS];      // row-min partials per j-slab (8 MB)
__device__ float g_p2[CSLABS][BB * MPTS];  // col-min partials (2 MB)

#define PACK2(o, lo, hi)   asm("mov.b64 %0,{%1,%2};" : "=l"(o) : "f"(lo), "f"(hi))
#define UNPACK2(lo, hi, i) asm("mov.b64 {%0,%1},%2;" : "=f"(lo), "=f"(hi) : "l"(i))
#define FMA2(d, a, b, c)   asm("fma.rn.f32x2 %0,%1,%2,%3;" : "=l"(d) : "l"(a), "l"(b), "l"(c))
#define ADD2(d, a, b)      asm("add.rn.f32x2 %0,%1,%2;" : "=l"(d) : "l"(a), "l"(b))

__global__ void __launch_bounds__(THREADS) chamfer_fused_kernel(
    const float* __restrict__ xyz1, const float* __restrict__ xyz2, float* __restrict__ out)
{
    __shared__ ulonglong2 tA[JCH];   // (-2x,-2x | -2y,-2y)
    __shared__ ulonglong2 tB[JCH];   // (-2z,-2z |  n2, n2)

    const int tid = threadIdx.x;
    const int lane = tid & 31;
    const int warp = tid >> 5;
    const int b = blockIdx.z;
    const int iBase = blockIdx.x * (THREADS * IPT);
    const int jBase = blockIdx.y * JCH;
    const float* __restrict__ P = xyz1 + (size_t)b * NPTS * 3;
    const float* __restrict__ Q = xyz2 + (size_t)b * MPTS * 3;

    if (blockIdx.x == 0 && blockIdx.y == 0 && blockIdx.z == 0 && tid == 0)
        out[0] = 0.f;

    u64 ax2[KKN], ay2[KKN], az2[KKN], n12[KKN];
    float mn[IPT];
#pragma unroll
    for (int kk = 0; kk < KKN; kk++) {
        int i0 = iBase + tid + (2 * kk) * THREADS;
        int i1 = iBase + tid + (2 * kk + 1) * THREADS;
        float x0 = P[i0 * 3], y0 = P[i0 * 3 + 1], z0 = P[i0 * 3 + 2];
        float x1 = P[i1 * 3], y1 = P[i1 * 3 + 1], z1 = P[i1 * 3 + 2];
        PACK2(ax2[kk], x0, x1);
        PACK2(ay2[kk], y0, y1);
        PACK2(az2[kk], z0, z1);
        float n0 = fmaf(x0, x0, fmaf(y0, y0, z0 * z0));
        float n1 = fmaf(x1, x1, fmaf(y1, y1, z1 * z1));
        PACK2(n12[kk], n0, n1);
        mn[2 * kk] = 3.4e38f;
        mn[2 * kk + 1] = 3.4e38f;
    }

    for (int jj = tid; jj < JCH; jj += THREADS) {
        int j = jBase + jj;
        float x = Q[j * 3], y = Q[j * 3 + 1], z = Q[j * 3 + 2];
        float n2 = fmaf(x, x, fmaf(y, y, z * z));
        float nx = -2.f * x, ny = -2.f * y, nz = -2.f * z;
        u64 X2, Y2, Z2, W2;
        PACK2(X2, nx, nx);
        PACK2(Y2, ny, ny);
        PACK2(Z2, nz, nz);
        PACK2(W2, n2, n2);
        tA[jj] = make_ulonglong2(X2, Y2);
        tB[jj] = make_ulonglong2(Z2, W2);
    }
    __syncthreads();

    float* __restrict__ colOut = g_p2[blockIdx.x * 4 + warp] + b * MPTS + jBase;

    for (int jj0 = 0; jj0 < JCH; jj0 += G) {
        int cvi[G];
#pragma unroll
        for (int g = 0; g < G; g++) {
            ulonglong2 ba = tA[jj0 + g];
            ulonglong2 bb = tB[jj0 + g];
            float c0 = 3.4e38f, c1 = 3.4e38f;
#pragma unroll
            for (int kk = 0; kk < KKN; kk++) {
                u64 w, t;
                ADD2(w, n12[kk], bb.y);        // n1 + n2
                FMA2(t, bb.x, az2[kk], w);     // += -2z*az
                FMA2(t, ba.y, ay2[kk], t);     // += -2y*ay
                FMA2(t, ba.x, ax2[kk], t);     // += -2x*ax -> dist^2 x2
                float t0, t1;
                UNPACK2(t0, t1, t);
                mn[2 * kk]     = fminf(mn[2 * kk], t0);
                mn[2 * kk + 1] = fminf(mn[2 * kk + 1], t1);
                c0 = fminf(c0, t0);
                c1 = fminf(c1, t1);
            }
            cvi[g] = __float_as_int(fmaxf(fminf(c0, c1), 0.f));  // clamp -> s32-ordered
        }
        // 8 independent REDUX.MIN warp reductions (pipelined)
#pragma unroll
        for (int g = 0; g < G; g++)
            cvi[g] = __reduce_min_sync(0xffffffffu, cvi[g]);
        int myv = cvi[0];
#pragma unroll
        for (int g = 1; g < G; g++)
            if (lane == g) myv = cvi[g];
        if (lane < G)
            colOut[jj0 + lane] = __int_as_float(myv);
    }

    float* __restrict__ rowOut = g_p1[blockIdx.y] + b * NPTS;
#pragma unroll
    for (int kk = 0; kk < KKN; kk++) {
        int i0 = iBase + tid + (2 * kk) * THREADS;
        int i1 = iBase + tid + (2 * kk + 1) * THREADS;
        rowOut[i0] = mn[2 * kk];
        rowOut[i1] = mn[2 * kk + 1];
    }
}

// 512 blocks x 256 threads. 8 threads per float4 column (q = gid&7):
// rows: each scans 8 of 64 slabs; cols: each scans 2 of 16 slabs.
__global__ void chamfer_reduce_kernel(float* __restrict__ out) {
    int gid = blockIdx.x * blockDim.x + threadIdx.x;   // 0..131071
    int col = gid >> 3;                                // 0..16383
    int q = gid & 7;
    float4 m = make_float4(3.4e38f, 3.4e38f, 3.4e38f, 3.4e38f);
    if (col < SLAB4) {
        const float4* base = (const float4*)g_p1[0] + col;
#pragma unroll
        for (int s = 0; s < JT / 8; s++) {
            float4 v = base[(size_t)(q * (JT / 8) + s) * SLAB4];
            m.x = fminf(m.x, v.x); m.y = fminf(m.y, v.y);
            m.z = fminf(m.z, v.z); m.w = fminf(m.w, v.w);
        }
    } else {
        const float4* base = (const float4*)g_p2[0] + (col - SLAB4);
#pragma unroll
        for (int s = 0; s < CSLABS / 8; s++) {
            float4 v = base[(size_t)(q * (CSLABS / 8) + s) * SLAB4];
            m.x = fminf(m.x, v.x); m.y = fminf(m.y, v.y);
            m.z = fminf(m.z, v.z); m.w = fminf(m.w, v.w);
        }
    }
    // combine 8 slab-shares (lanes differing in low 3 bits)
#pragma unroll
    for (int o = 1; o <= 4; o <<= 1) {
        m.x = fminf(m.x, __shfl_xor_sync(0xffffffffu, m.x, o));
        m.y = fminf(m.y, __shfl_xor_sync(0xffffffffu, m.y, o));
        m.z = fminf(m.z, __shfl_xor_sync(0xffffffffu, m.z, o));
        m.w = fminf(m.w, __shfl_xor_sync(0xffffffffu, m.w, o));
    }
    float s = (q == 0) ? ((m.x + m.y) + (m.z + m.w)) * (1.f / (BB * NPTS)) : 0.f;
#pragma unroll
    for (int o = 16; o > 0; o >>= 1) s += __shfl_down_sync(0xffffffffu, s, o);
    __shared__ float sh[8];
    if ((threadIdx.x & 31) == 0) sh[threadIdx.x >> 5] = s;
    __syncthreads();
    if (threadIdx.x < 8) {
        float v = sh[threadIdx.x];
#pragma unroll
        for (int o = 4; o > 0; o >>= 1) v += __shfl_down_sync(0xffu, v, o);
        if (threadIdx.x == 0) atomicAdd(out, v);
    }
}

extern "C" void kernel_launch(void* const* d_in, const int* in_sizes, int n_in,
                              void* d_out, int out_size) {
    const float* xyz1 = (const float*)d_in[0];
    const float* xyz2 = (const float*)d_in[1];
    float* out = (float*)d_out;

    dim3 grid(ITILES, JT, BB);  // (4, 64, 4) = 1024 blocks
    chamfer_fused_kernel<<<grid, THREADS>>>(xyz1, xyz2, out);

    chamfer_reduce_kernel<<<512, 256>>>(out);
}

// round 10
// speedup vs baseline: 1.1679x; 1.0399x over previous
#include <cuda_runtime.h>

// ChamferLoss fused single-pass, B=4, N=M=8192, 3D.
// Pair kernel (UNCHANGED from R9 — at the fp32 wide-fma floor): packed f32x2,
// deterministic partial buffers, REDUX.MIN.s32 col reduction.
// Reduce v3: coalesced lane->column mapping (32 consecutive float4 per warp),
// warp->slab-share split, smem cross-warp combine. Fixes R9's scattered loads.

#define BB 4
#define NPTS 8192
#define MPTS 8192
#define THREADS 128
#define IPT 16
#define KKN (IPT / 2)
#define ITILES (NPTS / (THREADS * IPT))   // 4
#define JT 64
#define JCH (MPTS / JT)                   // 128
#define G 8
#define CSLABS (ITILES * 4)               // 16 col slabs
#define SLAB4 (BB * NPTS / 4)             // 8192 float4 per slab

typedef unsigned long long u64;

__device__ float g_p1[JT][BB * NPTS];      // row-min partials per j-slab (8 MB)
__device__ float g_p2[CSLABS][BB * MPTS];  // col-min partials (2 MB)

#define PACK2(o, lo, hi)   asm("mov.b64 %0,{%1,%2};" : "=l"(o) : "f"(lo), "f"(hi))
#define UNPACK2(lo, hi, i) asm("mov.b64 {%0,%1},%2;" : "=f"(lo), "=f"(hi) : "l"(i))
#define FMA2(d, a, b, c)   asm("fma.rn.f32x2 %0,%1,%2,%3;" : "=l"(d) : "l"(a), "l"(b), "l"(c))
#define ADD2(d, a, b)      asm("add.rn.f32x2 %0,%1,%2;" : "=l"(d) : "l"(a), "l"(b))

__global__ void __launch_bounds__(THREADS) chamfer_fused_kernel(
    const float* __restrict__ xyz1, const float* __restrict__ xyz2, float* __restrict__ out)
{
    __shared__ ulonglong2 tA[JCH];
    __shared__ ulonglong2 tB[JCH];

    const int tid = threadIdx.x;
    const int lane = tid & 31;
    const int warp = tid >> 5;
    const int b = blockIdx.z;
    const int iBase = blockIdx.x * (THREADS * IPT);
    const int jBase = blockIdx.y * JCH;
    const float* __restrict__ P = xyz1 + (size_t)b * NPTS * 3;
    const float* __restrict__ Q = xyz2 + (size_t)b * MPTS * 3;

    if (blockIdx.x == 0 && blockIdx.y == 0 && blockIdx.z == 0 && tid == 0)
        out[0] = 0.f;

    u64 ax2[KKN], ay2[KKN], az2[KKN], n12[KKN];
    float mn[IPT];
#pragma unroll
    for (int kk = 0; kk < KKN; kk++) {
        int i0 = iBase + tid + (2 * kk) * THREADS;
        int i1 = iBase + tid + (2 * kk + 1) * THREADS;
        float x0 = P[i0 * 3], y0 = P[i0 * 3 + 1], z0 = P[i0 * 3 + 2];
        float x1 = P[i1 * 3], y1 = P[i1 * 3 + 1], z1 = P[i1 * 3 + 2];
        PACK2(ax2[kk], x0, x1);
        PACK2(ay2[kk], y0, y1);
        PACK2(az2[kk], z0, z1);
        float n0 = fmaf(x0, x0, fmaf(y0, y0, z0 * z0));
        float n1 = fmaf(x1, x1, fmaf(y1, y1, z1 * z1));
        PACK2(n12[kk], n0, n1);
        mn[2 * kk] = 3.4e38f;
        mn[2 * kk + 1] = 3.4e38f;
    }

    for (int jj = tid; jj < JCH; jj += THREADS) {
        int j = jBase + jj;
        float x = Q[j * 3], y = Q[j * 3 + 1], z = Q[j * 3 + 2];
        float n2 = fmaf(x, x, fmaf(y, y, z * z));
        float nx = -2.f * x, ny = -2.f * y, nz = -2.f * z;
        u64 X2, Y2, Z2, W2;
        PACK2(X2, nx, nx);
        PACK2(Y2, ny, ny);
        PACK2(Z2, nz, nz);
        PACK2(W2, n2, n2);
        tA[jj] = make_ulonglong2(X2, Y2);
        tB[jj] = make_ulonglong2(Z2, W2);
    }
    __syncthreads();

    float* __restrict__ colOut = g_p2[blockIdx.x * 4 + warp] + b * MPTS + jBase;

    for (int jj0 = 0; jj0 < JCH; jj0 += G) {
        int cvi[G];
#pragma unroll
        for (int g = 0; g < G; g++) {
            ulonglong2 ba = tA[jj0 + g];
            ulonglong2 bb = tB[jj0 + g];
            float c0 = 3.4e38f, c1 = 3.4e38f;
#pragma unroll
            for (int kk = 0; kk < KKN; kk++) {
                u64 w, t;
                ADD2(w, n12[kk], bb.y);        // n1 + n2
                FMA2(t, bb.x, az2[kk], w);     // += -2z*az
                FMA2(t, ba.y, ay2[kk], t);     // += -2y*ay
                FMA2(t, ba.x, ax2[kk], t);     // += -2x*ax -> dist^2 x2
                float t0, t1;
                UNPACK2(t0, t1, t);
                mn[2 * kk]     = fminf(mn[2 * kk], t0);
                mn[2 * kk + 1] = fminf(mn[2 * kk + 1], t1);
                c0 = fminf(c0, t0);
                c1 = fminf(c1, t1);
            }
            cvi[g] = __float_as_int(fmaxf(fminf(c0, c1), 0.f));
        }
#pragma unroll
        for (int g = 0; g < G; g++)
            cvi[g] = __reduce_min_sync(0xffffffffu, cvi[g]);
        int myv = cvi[0];
#pragma unroll
        for (int g = 1; g < G; g++)
            if (lane == g) myv = cvi[g];
        if (lane < G)
            colOut[jj0 + lane] = __int_as_float(myv);
    }

    float* __restrict__ rowOut = g_p1[blockIdx.y] + b * NPTS;
#pragma unroll
    for (int kk = 0; kk < KKN; kk++) {
        int i0 = iBase + tid + (2 * kk) * THREADS;
        int i1 = iBase + tid + (2 * kk + 1) * THREADS;
        rowOut[i0] = mn[2 * kk];
        rowOut[i1] = mn[2 * kk + 1];
    }
}

// Reduce v3: 512 blocks x 256 threads (8 warps).
// Blocks 0..255: row buffer; 256..511: col buffer.
// col4 = blkLocal*32 + lane (32 consecutive float4 -> coalesced 512B/warp/slab)
// warp w scans its slab share; smem combine; warp 0 finishes + atomicAdd.
__global__ void chamfer_reduce_kernel(float* __restrict__ out) {
    __shared__ float4 sm[8][32];
    const int lane = threadIdx.x & 31;
    const int warp = threadIdx.x >> 5;
    const bool isRow = blockIdx.x < 256;
    const int blkLocal = isRow ? blockIdx.x : blockIdx.x - 256;
    const int col4 = blkLocal * 32 + lane;

    float4 m = make_float4(3.4e38f, 3.4e38f, 3.4e38f, 3.4e38f);
    if (isRow) {
        const float4* base = (const float4*)g_p1[0] + col4;
#pragma unroll
        for (int s = 0; s < JT / 8; s++) {
            float4 v = base[(size_t)(warp * (JT / 8) + s) * SLAB4];
            m.x = fminf(m.x, v.x); m.y = fminf(m.y, v.y);
            m.z = fminf(m.z, v.z); m.w = fminf(m.w, v.w);
        }
    } else {
        const float4* base = (const float4*)g_p2[0] + col4;
#pragma unroll
        for (int s = 0; s < CSLABS / 8; s++) {
            float4 v = base[(size_t)(warp * (CSLABS / 8) + s) * SLAB4];
            m.x = fminf(m.x, v.x); m.y = fminf(m.y, v.y);
            m.z = fminf(m.z, v.z); m.w = fminf(m.w, v.w);
        }
    }
    sm[warp][lane] = m;
    __syncthreads();

    if (warp == 0) {
        float4 r = sm[0][lane];
#pragma unroll
        for (int w = 1; w < 8; w++) {
            float4 v = sm[w][lane];
            r.x = fminf(r.x, v.x); r.y = fminf(r.y, v.y);
            r.z = fminf(r.z, v.z); r.w = fminf(r.w, v.w);
        }
        float s = ((r.x + r.y) + (r.z + r.w)) * (1.f / (BB * NPTS));
#pragma unroll
        for (int o = 16; o > 0; o >>= 1)
            s += __shfl_down_sync(0xffffffffu, s, o);
        if (lane == 0) atomicAdd(out, s);
    }
}

extern "C" void kernel_launch(void* const* d_in, const int* in_sizes, int n_in,
                              void* d_out, int out_size) {
    const float* xyz1 = (const float*)d_in[0];
    const float* xyz2 = (const float*)d_in[1];
    float* out = (float*)d_out;

    dim3 grid(ITILES, JT, BB);  // (4, 64, 4) = 1024 blocks
    chamfer_fused_kernel<<<grid, THREADS>>>(xyz1, xyz2, out);

    chamfer_reduce_kernel<<<512, 256>>>(out);
}